// round 13
// baseline (speedup 1.0000x reference)
#include <cuda_runtime.h>
#include <cstdint>

// CrossCCC via packed fp32 FMA (fma.rn.f32x2 — 2 FMA per issue slot).
// Each thread owns 8 lag-pairs (16 lags); g pairs come from the raw g array
// (even start) or a one-float-shifted smem copy (odd start). 489 blocks,
// one 2048-chunk each; last block (atomic ticket) finalizes.

#define NL        256
#define NLAGS     250
#define CHUNK     2048
#define GWF       (CHUNK + 264)   // g window floats (needs CHUNK+256, padded)
#define NTHREADS  256
#define MAXBLK    640

typedef unsigned long long ull;

__device__ float d_Cpart[MAXBLK][NL];
__device__ float d_sums[MAXBLK][4];
__device__ unsigned int d_ticket;

__device__ __forceinline__ void ffma2(ull& acc, ull a, ull b) {
    asm("fma.rn.f32x2 %0, %1, %2, %0;" : "+l"(acc) : "l"(a), "l"(b));
}
__device__ __forceinline__ ull splat(float v) {
    ull r;
    asm("mov.b64 %0, {%1, %1};" : "=l"(r) : "r"(__float_as_uint(v)));
    return r;
}

__global__ void __launch_bounds__(NTHREADS, 4)
ccc_f32x2_kernel(const float* __restrict__ p, const float* __restrict__ g,
                 float* __restrict__ out, int T, int nchunks) {
    __shared__ __align__(16) float sp[CHUNK];
    __shared__ __align__(16) float sg[GWF];     // g window (even-start pairs)
    __shared__ __align__(16) float sgo[GWF];    // sgo[y] = sg[y+1] (odd-start pairs)
    __shared__ float Cblk[NL];
    __shared__ float red[NTHREADS / 32];
    __shared__ int   s_last;

    const int tid  = threadIdx.x;
    const int wid  = tid >> 5, lane = tid & 31;
    const int grp  = tid >> 4;          // 16 lag groups
    const int jsub = tid & 15;          // 16 j subthreads
    const int n0   = grp * 16;          // 16 lags per group

    ull acc[8];
#pragma unroll
    for (int i = 0; i < 8; i++) acc[i] = 0ull;
    float s_p = 0.f, q_p = 0.f, s_g = 0.f, q_g = 0.f;

    for (int c = blockIdx.x; c < nchunks; c += gridDim.x) {
        const long long base = (long long)c * CHUNK;
        __syncthreads();

        if (base + GWF <= (long long)T) {
            const float4* p4 = reinterpret_cast<const float4*>(p + base);
            const float4* g4 = reinterpret_cast<const float4*>(g + base);
#pragma unroll
            for (int i = tid; i < CHUNK / 4; i += NTHREADS) {
                float4 v = p4[i];
                *reinterpret_cast<float4*>(sp + 4 * i) = v;
                s_p += (v.x + v.y) + (v.z + v.w);
                q_p += (v.x * v.x + v.y * v.y) + (v.z * v.z + v.w * v.w);
            }
            for (int i = tid; i < GWF / 4; i += NTHREADS) {
                float4 v = g4[i];
                *reinterpret_cast<float4*>(sg + 4 * i) = v;
                if (i < CHUNK / 4) {
                    s_g += (v.x + v.y) + (v.z + v.w);
                    q_g += (v.x * v.x + v.y * v.y) + (v.z * v.z + v.w * v.w);
                }
            }
        } else {
            for (int i = tid; i < CHUNK; i += NTHREADS) {
                long long gi = base + i;
                float v = (gi < T) ? p[gi] : 0.f;
                sp[i] = v;
                s_p += v; q_p += v * v;
            }
            for (int i = tid; i < GWF; i += NTHREADS) {
                long long gi = base + i;
                float v = (gi < T) ? g[gi] : 0.f;
                sg[i] = v;
                if (i < CHUNK) { s_g += v; q_g += v * v; }
            }
        }
        __syncthreads();

        // build shifted copy: sgo[y] = sg[y+1]
        for (int i = tid; i < GWF / 4 - 1; i += NTHREADS) {
            float4 f = *reinterpret_cast<const float4*>(sg + 4 * i);
            float f4 = sg[4 * i + 4];
            *reinterpret_cast<float4*>(sgo + 4 * i) =
                make_float4(f.y, f.z, f.w, f4);
        }
        __syncthreads();

        // ---- mainloop: 8 j x 8 lag-pairs per iteration ----
        for (int k0 = 0; k0 < CHUNK; k0 += 128) {
            const int jb = k0 + 8 * jsub;
            float4 pA = *reinterpret_cast<const float4*>(sp + jb);
            float4 pB = *reinterpret_cast<const float4*>(sp + jb + 4);
            const float pf[8] = {pA.x, pA.y, pA.z, pA.w, pB.x, pB.y, pB.z, pB.w};
            const int e0 = (jb + n0) >> 1;   // (jb+n0) is even
            const ull* geP = reinterpret_cast<const ull*>(sg)  + e0;
            const ull* goP = reinterpret_cast<const ull*>(sgo) + e0;

            // even dj = 2h : pairs ge[e0+h .. e0+h+7]
            {
                ull w[11];
#pragma unroll
                for (int q = 0; q < 11; q++) w[q] = geP[q];
#pragma unroll
                for (int h = 0; h < 4; h++) {
                    ull a = splat(pf[2 * h]);
#pragma unroll
                    for (int i = 0; i < 8; i++) ffma2(acc[i], a, w[h + i]);
                }
            }
            // odd dj = 2h+1 : pairs go[e0+h .. e0+h+7]
            {
                ull w[11];
#pragma unroll
                for (int q = 0; q < 11; q++) w[q] = goP[q];
#pragma unroll
                for (int h = 0; h < 4; h++) {
                    ull a = splat(pf[2 * h + 1]);
#pragma unroll
                    for (int i = 0; i < 8; i++) ffma2(acc[i], a, w[h + i]);
                }
            }
        }
    }
    __syncthreads();

    // ---- reduce accs across the 16 jsub lanes of each group ----
#pragma unroll
    for (int i = 0; i < 8; i++) {
        float lo = __uint_as_float((unsigned)(acc[i] & 0xFFFFFFFFull));
        float hi = __uint_as_float((unsigned)(acc[i] >> 32));
#pragma unroll
        for (int m = 8; m > 0; m >>= 1) {
            lo += __shfl_xor_sync(0xFFFFFFFFu, lo, m);
            hi += __shfl_xor_sync(0xFFFFFFFFu, hi, m);
        }
        if (jsub == 0) {
            Cblk[n0 + 2 * i]     = lo;
            Cblk[n0 + 2 * i + 1] = hi;
        }
    }
    __syncthreads();
    if (tid < NL) d_Cpart[blockIdx.x][tid] = Cblk[tid];

    // ---- block-reduce scalar sums ----
    float vals[4] = {s_p, q_p, s_g, q_g};
    for (int v = 0; v < 4; v++) {
        float x = vals[v];
#pragma unroll
        for (int off = 16; off > 0; off >>= 1)
            x += __shfl_down_sync(0xFFFFFFFFu, x, off);
        if (lane == 0) red[wid] = x;
        __syncthreads();
        if (tid == 0) {
            float s = 0.f;
            for (int w = 0; w < NTHREADS / 32; w++) s += red[w];
            d_sums[blockIdx.x][v] = s;
        }
        __syncthreads();
    }

    // ---- last-block election ----
    __threadfence();
    if (tid == 0) {
        unsigned int old = atomicAdd(&d_ticket, 1u);
        s_last = (old == gridDim.x - 1) ? 1 : 0;
    }
    __syncthreads();
    if (!s_last) return;

    // ================= finalize (last block) =================
    const int nblk = gridDim.x;
    __shared__ double sh_sums[4];
    __shared__ double prefp[NL];
    __shared__ double prefq[NL];
    __shared__ double cccsh[NL];

    double Cn = 0.0;
    if (tid < NL) {
        const int lag = tid;
        float a0 = 0.f, a1 = 0.f, a2 = 0.f, a3 = 0.f;
        int b = 0;
        for (; b + 3 < nblk; b += 4) {
            a0 += d_Cpart[b    ][lag];
            a1 += d_Cpart[b + 1][lag];
            a2 += d_Cpart[b + 2][lag];
            a3 += d_Cpart[b + 3][lag];
        }
        for (; b < nblk; b++) a0 += d_Cpart[b][lag];
        Cn = (double)((a0 + a1) + (a2 + a3));
    }

    if (tid < 128) {
        int v = tid >> 5, ln = tid & 31;
        double sv = 0.0;
        for (int b = ln; b < nblk; b += 32) sv += (double)d_sums[b][v];
#pragma unroll
        for (int off = 16; off > 0; off >>= 1)
            sv += __shfl_down_sync(0xFFFFFFFFu, sv, off);
        if (ln == 0) sh_sums[v] = sv;
    }

    if (tid < NL) {
        double w = (tid >= 1) ? (double)p[T - tid] : 0.0;
        prefp[tid] = w;
        prefq[tid] = w * w;
    }
    __syncthreads();
#pragma unroll
    for (int off = 1; off < NL; off <<= 1) {
        double a = 0.0, b = 0.0;
        if (tid < NL && tid >= off) { a = prefp[tid - off]; b = prefq[tid - off]; }
        __syncthreads();
        if (tid < NL) { prefp[tid] += a; prefq[tid] += b; }
        __syncthreads();
    }

    double ccc = 0.0;
    if (tid < NLAGS) {
        double tp = prefp[tid], tq = prefq[tid];
        const double Td  = (double)T;
        const double rT  = 1.0 / Td;
        const double rT1 = 1.0 / (Td - 1.0);
        double Sp = sh_sums[0] - tp, Qp = sh_sums[1] - tq;
        double Sg = sh_sums[2],      Qg = sh_sums[3];
        double mean_gt   = Sg * rT;
        double var_gt    = (Qg - Sg * Sg * rT) * rT1;
        double mean_pred = Sp * rT;
        double var_pred  = (Qp - Sp * Sp * rT) * rT1;
        double cov       = (Cn - mean_gt * Sp) * rT;
        double dm        = mean_gt - mean_pred;
        ccc = 2.0 * cov / (var_gt + var_pred + dm * dm);
    }
    if (tid < NL) cccsh[tid] = ccc;
    __syncthreads();
#pragma unroll
    for (int off = NL / 2; off > 0; off >>= 1) {
        if (tid < off) cccsh[tid] += cccsh[tid + off];
        __syncthreads();
    }
    if (tid == 0) {
        out[0] = (float)(1.0 - cccsh[0] / (double)NLAGS);
        d_ticket = 0;
    }
}

extern "C" void kernel_launch(void* const* d_in, const int* in_sizes, int n_in,
                              void* d_out, int out_size) {
    const float* p = (const float*)d_in[0];
    const float* g = (const float*)d_in[1];
    int T = in_sizes[0];
    int nchunks = (T + CHUNK - 1) / CHUNK;
    int grid = nchunks < 592 ? nchunks : 592;
    if (grid > MAXBLK) grid = MAXBLK;
    ccc_f32x2_kernel<<<grid, NTHREADS>>>(p, g, (float*)d_out, T, nchunks);
}

// round 14
// speedup vs baseline: 1.2610x; 1.2610x over previous
#include <cuda_runtime.h>
#include <cstdint>

// CrossCCC via packed fp32 FMA (fma.rn.f32x2 - 2 FMA per issue slot).
// Lag-pair accumulators; g pairs read from PADDED smem arrays
// (loc(s) = s + s/4 -> lane stride 5 ull, gcd(5,16)=1 -> conflict-free
// 2-phase LDS.64). e0 is 4-aligned so per-q padded offsets are constants.
// 489 blocks, one 2048-chunk each; last block (atomic ticket) finalizes.

#define NL        256
#define NLAGS     250
#define CHUNK     2048
#define GWF       2312            // g window floats (needs 2303)
#define GUL       (GWF / 2)       // 1156 ull pairs
#define PADU      1456            // padded ull capacity (1156*5/4 = 1445)
#define NTHREADS  256
#define MAXBLK    640
#define PLOC(q)   ((q) + ((q) >> 2))

typedef unsigned long long ull;

__device__ float d_Cpart[MAXBLK][NL];
__device__ float d_sums[MAXBLK][4];
__device__ unsigned int d_ticket;

__device__ __forceinline__ void ffma2(ull& acc, ull a, ull b) {
    asm("fma.rn.f32x2 %0, %1, %2, %0;" : "+l"(acc) : "l"(a), "l"(b));
}
__device__ __forceinline__ ull splat(float v) {
    ull r;
    asm("mov.b64 %0, {%1, %1};" : "=l"(r) : "r"(__float_as_uint(v)));
    return r;
}
__device__ __forceinline__ ull packf2(float lo, float hi) {
    ull r;
    asm("mov.b64 %0, {%1, %2};" : "=l"(r) : "r"(__float_as_uint(lo)), "r"(__float_as_uint(hi)));
    return r;
}

__global__ void __launch_bounds__(NTHREADS, 4)
ccc_f32x2_kernel(const float* __restrict__ p, const float* __restrict__ g,
                 float* __restrict__ out, int T, int nchunks) {
    __shared__ __align__(16) float sp[CHUNK];
    __shared__ __align__(16) float sgl[GWF + 4];   // linear staging
    __shared__ __align__(16) ull   sgp[PADU];      // even-start pairs, padded
    __shared__ __align__(16) ull   sgop[PADU];     // odd-start pairs, padded
    __shared__ float Cblk[NL];
    __shared__ float red[NTHREADS / 32];
    __shared__ int   s_last;

    const int tid  = threadIdx.x;
    const int wid  = tid >> 5, lane = tid & 31;
    const int grp  = tid >> 4;          // 16 lag groups (16 lags each)
    const int jsub = tid & 15;          // 16 j subthreads
    const int n0   = grp * 16;

    ull acc[8];
#pragma unroll
    for (int i = 0; i < 8; i++) acc[i] = 0ull;
    float s_p = 0.f, q_p = 0.f, s_g = 0.f, q_g = 0.f;

    for (int c = blockIdx.x; c < nchunks; c += gridDim.x) {
        const long long base = (long long)c * CHUNK;
        __syncthreads();

        // ---- fill sp + linear g staging (stats ride along) ----
        if (base + GWF + 4 <= (long long)T) {
            const float4* p4 = reinterpret_cast<const float4*>(p + base);
            const float4* g4 = reinterpret_cast<const float4*>(g + base);
#pragma unroll
            for (int i = tid; i < CHUNK / 4; i += NTHREADS) {
                float4 v = p4[i];
                *reinterpret_cast<float4*>(sp + 4 * i) = v;
                s_p += (v.x + v.y) + (v.z + v.w);
                q_p += (v.x * v.x + v.y * v.y) + (v.z * v.z + v.w * v.w);
            }
            for (int i = tid; i < GWF / 4; i += NTHREADS) {
                float4 v = g4[i];
                *reinterpret_cast<float4*>(sgl + 4 * i) = v;
                if (i < CHUNK / 4) {
                    s_g += (v.x + v.y) + (v.z + v.w);
                    q_g += (v.x * v.x + v.y * v.y) + (v.z * v.z + v.w * v.w);
                }
            }
        } else {
            for (int i = tid; i < CHUNK; i += NTHREADS) {
                long long gi = base + i;
                float v = (gi < T) ? p[gi] : 0.f;
                sp[i] = v;
                s_p += v; q_p += v * v;
            }
            for (int i = tid; i < GWF; i += NTHREADS) {
                long long gi = base + i;
                float v = (gi < T) ? g[gi] : 0.f;
                sgl[i] = v;
                if (i < CHUNK) { s_g += v; q_g += v * v; }
            }
        }
        if (tid < 4) sgl[GWF + tid] = 0.f;
        __syncthreads();

        // ---- build padded pair arrays ----
        for (int s = tid; s < GUL; s += NTHREADS) {
            float a = sgl[2 * s], b = sgl[2 * s + 1], d = sgl[2 * s + 2];
            int loc = s + (s >> 2);
            sgp[loc]  = packf2(a, b);
            sgop[loc] = packf2(b, d);
        }
        __syncthreads();

        // ---- mainloop: 8 j x 8 lag-pairs per 128-j block ----
        for (int k0 = 0; k0 < CHUNK; k0 += 128) {
            const int jb = k0 + 8 * jsub;
            float4 pA = *reinterpret_cast<const float4*>(sp + jb);
            float4 pB = *reinterpret_cast<const float4*>(sp + jb + 4);
            const float pf[8] = {pA.x, pA.y, pA.z, pA.w, pB.x, pB.y, pB.z, pB.w};
            const int e0 = (jb + n0) >> 1;        // multiple of 4
            const int eb = e0 + (e0 >> 2);        // padded base

            // even dj = 2h : pairs at e0 + h + i
            {
                ull w[11];
#pragma unroll
                for (int q = 0; q < 11; q++) w[q] = sgp[eb + PLOC(q)];
#pragma unroll
                for (int h = 0; h < 4; h++) {
                    ull a = splat(pf[2 * h]);
#pragma unroll
                    for (int i = 0; i < 8; i++) ffma2(acc[i], a, w[h + i]);
                }
            }
            // odd dj = 2h+1 : shifted pairs at e0 + h + i
            {
                ull w[11];
#pragma unroll
                for (int q = 0; q < 11; q++) w[q] = sgop[eb + PLOC(q)];
#pragma unroll
                for (int h = 0; h < 4; h++) {
                    ull a = splat(pf[2 * h + 1]);
#pragma unroll
                    for (int i = 0; i < 8; i++) ffma2(acc[i], a, w[h + i]);
                }
            }
        }
    }
    __syncthreads();

    // ---- reduce accs across the 16 jsub lanes of each group ----
#pragma unroll
    for (int i = 0; i < 8; i++) {
        float lo = __uint_as_float((unsigned)(acc[i] & 0xFFFFFFFFull));
        float hi = __uint_as_float((unsigned)(acc[i] >> 32));
#pragma unroll
        for (int m = 8; m > 0; m >>= 1) {
            lo += __shfl_xor_sync(0xFFFFFFFFu, lo, m);
            hi += __shfl_xor_sync(0xFFFFFFFFu, hi, m);
        }
        if (jsub == 0) {
            Cblk[n0 + 2 * i]     = lo;
            Cblk[n0 + 2 * i + 1] = hi;
        }
    }
    __syncthreads();
    if (tid < NL) d_Cpart[blockIdx.x][tid] = Cblk[tid];

    // ---- block-reduce scalar sums ----
    float vals[4] = {s_p, q_p, s_g, q_g};
    for (int v = 0; v < 4; v++) {
        float x = vals[v];
#pragma unroll
        for (int off = 16; off > 0; off >>= 1)
            x += __shfl_down_sync(0xFFFFFFFFu, x, off);
        if (lane == 0) red[wid] = x;
        __syncthreads();
        if (tid == 0) {
            float s = 0.f;
            for (int w = 0; w < NTHREADS / 32; w++) s += red[w];
            d_sums[blockIdx.x][v] = s;
        }
        __syncthreads();
    }

    // ---- last-block election ----
    __threadfence();
    if (tid == 0) {
        unsigned int old = atomicAdd(&d_ticket, 1u);
        s_last = (old == gridDim.x - 1) ? 1 : 0;
    }
    __syncthreads();
    if (!s_last) return;

    // ================= finalize (last block) =================
    const int nblk = gridDim.x;
    __shared__ double sh_sums[4];
    __shared__ double prefp[NL];
    __shared__ double prefq[NL];
    __shared__ double cccsh[NL];

    double Cn = 0.0;
    if (tid < NL) {
        const int lag = tid;
        float a0 = 0.f, a1 = 0.f, a2 = 0.f, a3 = 0.f;
        int b = 0;
        for (; b + 3 < nblk; b += 4) {
            a0 += d_Cpart[b    ][lag];
            a1 += d_Cpart[b + 1][lag];
            a2 += d_Cpart[b + 2][lag];
            a3 += d_Cpart[b + 3][lag];
        }
        for (; b < nblk; b++) a0 += d_Cpart[b][lag];
        Cn = (double)((a0 + a1) + (a2 + a3));
    }

    if (tid < 128) {
        int v = tid >> 5, ln = tid & 31;
        double sv = 0.0;
        for (int b = ln; b < nblk; b += 32) sv += (double)d_sums[b][v];
#pragma unroll
        for (int off = 16; off > 0; off >>= 1)
            sv += __shfl_down_sync(0xFFFFFFFFu, sv, off);
        if (ln == 0) sh_sums[v] = sv;
    }

    if (tid < NL) {
        double w = (tid >= 1) ? (double)p[T - tid] : 0.0;
        prefp[tid] = w;
        prefq[tid] = w * w;
    }
    __syncthreads();
#pragma unroll
    for (int off = 1; off < NL; off <<= 1) {
        double a = 0.0, b = 0.0;
        if (tid < NL && tid >= off) { a = prefp[tid - off]; b = prefq[tid - off]; }
        __syncthreads();
        if (tid < NL) { prefp[tid] += a; prefq[tid] += b; }
        __syncthreads();
    }

    double ccc = 0.0;
    if (tid < NLAGS) {
        double tp = prefp[tid], tq = prefq[tid];
        const double Td  = (double)T;
        const double rT  = 1.0 / Td;
        const double rT1 = 1.0 / (Td - 1.0);
        double Sp = sh_sums[0] - tp, Qp = sh_sums[1] - tq;
        double Sg = sh_sums[2],      Qg = sh_sums[3];
        double mean_gt   = Sg * rT;
        double var_gt    = (Qg - Sg * Sg * rT) * rT1;
        double mean_pred = Sp * rT;
        double var_pred  = (Qp - Sp * Sp * rT) * rT1;
        double cov       = (Cn - mean_gt * Sp) * rT;
        double dm        = mean_gt - mean_pred;
        ccc = 2.0 * cov / (var_gt + var_pred + dm * dm);
    }
    if (tid < NL) cccsh[tid] = ccc;
    __syncthreads();
#pragma unroll
    for (int off = NL / 2; off > 0; off >>= 1) {
        if (tid < off) cccsh[tid] += cccsh[tid + off];
        __syncthreads();
    }
    if (tid == 0) {
        out[0] = (float)(1.0 - cccsh[0] / (double)NLAGS);
        d_ticket = 0;
    }
}

extern "C" void kernel_launch(void* const* d_in, const int* in_sizes, int n_in,
                              void* d_out, int out_size) {
    const float* p = (const float*)d_in[0];
    const float* g = (const float*)d_in[1];
    int T = in_sizes[0];
    int nchunks = (T + CHUNK - 1) / CHUNK;
    int grid = nchunks < 592 ? nchunks : 592;
    if (grid > MAXBLK) grid = MAXBLK;
    ccc_f32x2_kernel<<<grid, NTHREADS>>>(p, g, (float*)d_out, T, nchunks);
}

// round 15
// speedup vs baseline: 1.6983x; 1.3468x over previous
#include <cuda_runtime.h>
#include <cstdint>

// CrossCCC via tf32 mma.sync.m16n8k8 + cp.async double-buffered tiles.
//   j = base + 128k + m  =>  C(n) = sum_st sum_m D_st[m][m+n]
//   pa[k][m] = p[base+128k+m]  (16 x 128 fp32, k-major rows: contiguous gmem)
//   gb[k][u] = g[base+128k+u]  (16 x 384 fp32, contiguous gmem rows)
// Banded N: warp (m-tile mi, quarter q) computes tiles u0 = m0+8*(toff[q]+t);
// diagonal lags accumulate in MMA D registers (indep per tile), scattered to
// smem once at kernel end. Last block (atomic ticket) finalizes.

#define NL        256
#define NLAGS     250
#define KROWS     16
#define SUPER     2048
#define PAW       132                 // pa row stride (floats)
#define GBW       388                 // gb row stride (floats)
#define PA_F      (KROWS * PAW)       // 2112
#define GB_F      (KROWS * GBW)       // 6208
#define BUF_F     (PA_F + GB_F)       // 8320 floats per buffer
#define SMEM_BYTES (2 * BUF_F * 4)    // 66560
#define CSW       264                 // Cs row stride (8 mod 32 rotation)
#define NTHREADS  1024
#define MAXBLK    160

__device__ float d_Cpart[MAXBLK][NL];
__device__ float d_sums[MAXBLK][4];
__device__ unsigned int d_ticket;

__device__ __forceinline__ void mma_tf32(float& d0, float& d1, float& d2, float& d3,
                                         uint32_t a0, uint32_t a1, uint32_t a2, uint32_t a3,
                                         uint32_t b0, uint32_t b1) {
    asm volatile(
        "mma.sync.aligned.m16n8k8.row.col.f32.tf32.tf32.f32 "
        "{%0,%1,%2,%3}, {%4,%5,%6,%7}, {%8,%9}, {%0,%1,%2,%3};"
        : "+f"(d0), "+f"(d1), "+f"(d2), "+f"(d3)
        : "r"(a0), "r"(a1), "r"(a2), "r"(a3), "r"(b0), "r"(b1));
}
__device__ __forceinline__ void cpa16(uint32_t dst_smem, const float* src) {
    asm volatile("cp.async.cg.shared.global [%0], [%1], 16;"
                 :: "r"(dst_smem), "l"(src) : "memory");
}
__device__ __forceinline__ uint32_t smem_u32(const void* ptr) {
    uint32_t a;
    asm("{ .reg .u64 t; cvta.to.shared.u64 t, %1; cvt.u32.u64 %0, t; }"
        : "=r"(a) : "l"(ptr));
    return a;
}

// fill one supertile's tiles (buffer fl) for chunk base; cp.async when safe
__device__ __forceinline__ void fill_tiles(float* pab, float* gbb,
                                           const float* p, const float* g,
                                           long long base, int T, int tid) {
    if (base + (long long)(128 * (KROWS - 1) + 384) <= (long long)T) {
        if (tid < 512) {                       // pa: 512 x 16B
            int k = tid >> 5, seg = tid & 31;
            cpa16(smem_u32(pab + k * PAW + 4 * seg), p + base + 128 * k + 4 * seg);
        }
        for (int idx = tid; idx < 1536; idx += NTHREADS) {  // gb: 1536 x 16B
            int k = idx / 96, seg = idx - 96 * k;
            cpa16(smem_u32(gbb + k * GBW + 4 * seg), g + base + 128 * k + 4 * seg);
        }
    } else {
        for (int idx = tid; idx < 2048; idx += NTHREADS) {
            int k = idx >> 7, m = idx & 127;
            long long gi = base + idx;
            pab[k * PAW + m] = (gi < T) ? p[gi] : 0.f;
        }
        for (int idx = tid; idx < KROWS * 384; idx += NTHREADS) {
            int k = idx / 384, u = idx - 384 * k;
            long long gi = base + 128 * k + u;
            gbb[k * GBW + u] = (gi < T) ? g[gi] : 0.f;
        }
    }
    asm volatile("cp.async.commit_group;" ::: "memory");
}

__global__ void __launch_bounds__(NTHREADS, 1)
ccc_tf32_kernel(const float* __restrict__ p, const float* __restrict__ g,
                float* __restrict__ out, int T, int nst) {
    extern __shared__ float sm[];
    float* Cs = sm;                    // [32][CSW], aliases tiles post-mainloop

    __shared__ float Cfold[4][NL];
    __shared__ float red[NTHREADS / 32];
    __shared__ int   s_last;

    const int tid  = threadIdx.x;
    const int wid  = tid >> 5, lane = tid & 31;
    const int gid  = lane >> 2, tig = lane & 3;
    const int mi   = wid & 7, q = wid >> 3;
    const int m0   = mi * 16;
    const int toff = (q == 0) ? 0 : (q == 1) ? 9 : (q == 2) ? 18 : 26;
    const int ntq  = (q < 2) ? 9 : 8;

    float acc0[10], acc1[10];
#pragma unroll
    for (int s = 0; s < 10; s++) { acc0[s] = 0.f; acc1[s] = 0.f; }
    float s_p = 0.f, q_p = 0.f, s_g = 0.f, q_g = 0.f;

    // prologue prefetch of this block's first chunk
    int buf = 0;
    if (blockIdx.x < (unsigned)nst)
        fill_tiles(sm, sm + PA_F, p, g, (long long)blockIdx.x * SUPER, T, tid);

    for (int c = blockIdx.x; c < nst; c += gridDim.x) {
        asm volatile("cp.async.wait_group 0;" ::: "memory");
        __syncthreads();

        const float* pab = sm + buf * BUF_F;
        const float* gbb = pab + PA_F;

        // prefetch next chunk into the other buffer (overlaps compute below)
        int nc = c + gridDim.x;
        if (nc < nst) {
            float* npa = sm + (buf ^ 1) * BUF_F;
            fill_tiles(npa, npa + PA_F, p, g, (long long)nc * SUPER, T, tid);
        }

        // ---- stats from smem (2 elements each of p,g per thread) ----
#pragma unroll
        for (int it = 0; it < 2; it++) {
            int i = tid + it * NTHREADS;
            int k = i >> 7, m = i & 127;
            float v = pab[k * PAW + m];
            s_p += v; q_p += v * v;
            float w = gbb[k * GBW + m];
            s_g += w; q_g += w * w;
        }

        // ---- A fragments (2 k8-steps) ----
        uint32_t af[2][4];
#pragma unroll
        for (int ks = 0; ks < 2; ks++) {
            int kr = 8 * ks + tig;
            af[ks][0] = __float_as_uint(pab[kr * PAW + m0 + gid]);
            af[ks][1] = __float_as_uint(pab[kr * PAW + m0 + gid + 8]);
            af[ks][2] = __float_as_uint(pab[(kr + 4) * PAW + m0 + gid]);
            af[ks][3] = __float_as_uint(pab[(kr + 4) * PAW + m0 + gid + 8]);
        }

        // ---- banded tiles: u0 = m0 + 8*(toff+t) ----
#pragma unroll
        for (int t = 0; t < 9; t++) {
            if (t < ntq) {
                const int uc = m0 + 8 * (toff + t) + gid;
                float d0 = 0.f, d1 = 0.f, d2 = 0.f, d3 = 0.f;
#pragma unroll
                for (int ks = 0; ks < 2; ks++) {
                    int kr = 8 * ks + tig;
                    uint32_t b0 = __float_as_uint(gbb[kr * GBW + uc]);
                    uint32_t b1 = __float_as_uint(gbb[(kr + 4) * GBW + uc]);
                    mma_tf32(d0, d1, d2, d3,
                             af[ks][0], af[ks][1], af[ks][2], af[ks][3], b0, b1);
                }
                acc0[t + 1] += d0;
                acc1[t + 1] += d1;
                acc0[t]     += d2;
                acc1[t]     += d3;
            }
        }
        buf ^= 1;
    }
    __syncthreads();   // tiles dead; Cs aliases them

    // ---- zero Cs and scatter accumulators (once) ----
    for (int i = tid; i < 32 * CSW; i += NTHREADS) Cs[i] = 0.f;
    __syncthreads();
    {
        float* Crow = Cs + wid * CSW;
        const int bn = 8 * toff + 2 * tig - gid;
#pragma unroll
        for (int ph = 0; ph < 4; ph++) {
            if (tig == ph) {
#pragma unroll
                for (int s = 0; s < 10; s++) {
                    if (s <= ntq) {
                        int n = bn + 8 * s - 8;
                        if ((unsigned)n < NLAGS) Crow[n] += acc0[s];
                        if ((unsigned)(n + 1) < NLAGS) Crow[n + 1] += acc1[s];
                    }
                }
            }
            __syncwarp();
        }
    }
    __syncthreads();

    // ---- fold 32 rows -> d_Cpart ----
    {
        int n = tid & 255, part = tid >> 8;   // 0..3
        float v = 0.f;
#pragma unroll
        for (int r = 0; r < 8; r++) v += Cs[(part * 8 + r) * CSW + n];
        Cfold[part][n] = v;
    }
    __syncthreads();
    if (tid < NL)
        d_Cpart[blockIdx.x][tid] = (Cfold[0][tid] + Cfold[1][tid])
                                 + (Cfold[2][tid] + Cfold[3][tid]);

    // ---- block-reduce scalar sums ----
    float vals[4] = {s_p, q_p, s_g, q_g};
    for (int v = 0; v < 4; v++) {
        float x = vals[v];
#pragma unroll
        for (int off = 16; off > 0; off >>= 1)
            x += __shfl_down_sync(0xFFFFFFFFu, x, off);
        if (lane == 0) red[wid] = x;
        __syncthreads();
        if (tid == 0) {
            float s = 0.f;
            for (int w = 0; w < NTHREADS / 32; w++) s += red[w];
            d_sums[blockIdx.x][v] = s;
        }
        __syncthreads();
    }

    // ---- last-block election ----
    __threadfence();
    if (tid == 0) {
        unsigned int old = atomicAdd(&d_ticket, 1u);
        s_last = (old == gridDim.x - 1) ? 1 : 0;
    }
    __syncthreads();
    if (!s_last) return;

    // ================= finalize (last block) =================
    const int nblk = gridDim.x;
    __shared__ double sh_sums[4];
    __shared__ double prefp[NL];
    __shared__ double prefq[NL];
    __shared__ double cccsh[NL];

    double Cn = 0.0;
    if (tid < NL) {
        const int lag = tid;
        float a0 = 0.f, a1 = 0.f, a2 = 0.f, a3 = 0.f;
        int b = 0;
        for (; b + 3 < nblk; b += 4) {
            a0 += d_Cpart[b    ][lag];
            a1 += d_Cpart[b + 1][lag];
            a2 += d_Cpart[b + 2][lag];
            a3 += d_Cpart[b + 3][lag];
        }
        for (; b < nblk; b++) a0 += d_Cpart[b][lag];
        Cn = (double)((a0 + a1) + (a2 + a3));
    }

    if (tid < 128) {
        int v = tid >> 5, ln = tid & 31;
        double sv = 0.0;
        for (int b = ln; b < nblk; b += 32) sv += (double)d_sums[b][v];
#pragma unroll
        for (int off = 16; off > 0; off >>= 1)
            sv += __shfl_down_sync(0xFFFFFFFFu, sv, off);
        if (ln == 0) sh_sums[v] = sv;
    }

    if (tid < NL) {
        double w = (tid >= 1) ? (double)p[T - tid] : 0.0;
        prefp[tid] = w;
        prefq[tid] = w * w;
    }
    __syncthreads();
#pragma unroll
    for (int off = 1; off < NL; off <<= 1) {
        double a = 0.0, b = 0.0;
        if (tid < NL && tid >= off) { a = prefp[tid - off]; b = prefq[tid - off]; }
        __syncthreads();
        if (tid < NL) { prefp[tid] += a; prefq[tid] += b; }
        __syncthreads();
    }

    double ccc = 0.0;
    if (tid < NLAGS) {
        double tp = prefp[tid], tq = prefq[tid];
        const double Td  = (double)T;
        const double rT  = 1.0 / Td;
        const double rT1 = 1.0 / (Td - 1.0);
        double Sp = sh_sums[0] - tp, Qp = sh_sums[1] - tq;
        double Sg = sh_sums[2],      Qg = sh_sums[3];
        double mean_gt   = Sg * rT;
        double var_gt    = (Qg - Sg * Sg * rT) * rT1;
        double mean_pred = Sp * rT;
        double var_pred  = (Qp - Sp * Sp * rT) * rT1;
        double cov       = (Cn - mean_gt * Sp) * rT;
        double dm        = mean_gt - mean_pred;
        ccc = 2.0 * cov / (var_gt + var_pred + dm * dm);
    }
    if (tid < NL) cccsh[tid] = ccc;
    __syncthreads();
#pragma unroll
    for (int off = NL / 2; off > 0; off >>= 1) {
        if (tid < off) cccsh[tid] += cccsh[tid + off];
        __syncthreads();
    }
    if (tid == 0) {
        out[0] = (float)(1.0 - cccsh[0] / (double)NLAGS);
        d_ticket = 0;
    }
}

extern "C" void kernel_launch(void* const* d_in, const int* in_sizes, int n_in,
                              void* d_out, int out_size) {
    const float* p = (const float*)d_in[0];
    const float* g = (const float*)d_in[1];
    int T = in_sizes[0];
    int nst = (T + SUPER - 1) / SUPER;
    int grid = nst < 148 ? nst : 148;
    cudaFuncSetAttribute(ccc_tf32_kernel,
                         cudaFuncAttributeMaxDynamicSharedMemorySize, SMEM_BYTES);
    ccc_tf32_kernel<<<grid, NTHREADS, SMEM_BYTES>>>(p, g, (float*)d_out, T, nst);
}